// round 1
// baseline (speedup 1.0000x reference)
#include <cuda_runtime.h>
#include <math.h>

#define E_EDGES 90112
#define F 16
#define N0 1408

// ---------------- persistent device scratch (no allocation allowed) ----------------
__device__ float g_h[N0 * F];        // h = x @ W for current layer
__device__ float g_out[N0 * F];      // aggregated conv output for current layer
__device__ float g_xr[N0 * F];       // relu'd conv output (pre-pool)
__device__ float g_xp[4][704 * F];   // pooled node features per layer (max k = 704)
__device__ float g_deg[4][N0];       // per-layer degree (init 1.0 = self loop)
__device__ float g_dinv[N0];         // per-layer inverse-sqrt degree (reused)
__device__ int   g_pos[N0];          // old->new node index map (reused)
__device__ int   g_row[4][E_EDGES];
__device__ int   g_col[4][E_EDGES];
__device__ float g_ew [4][E_EDGES];
__device__ float g_h1[1024];
__device__ float g_h2[512];

// ---------------- K0: per-replay init ----------------
__global__ void k_init(const int* __restrict__ edge_index, float* __restrict__ out96) {
    int idx = blockIdx.x * blockDim.x + threadIdx.x;
    if (idx < E_EDGES) {
        g_row[0][idx] = edge_index[idx];
        g_col[0][idx] = edge_index[E_EDGES + idx];
        g_ew[0][idx]  = 1.0f;
    }
    if (idx < 4 * N0) ((float*)g_deg)[idx] = 1.0f;   // self-loop weight pre-seeded
    if (idx < 1024) g_h1[idx] = 0.0f;
    if (idx < 512)  g_h2[idx] = 0.0f;
    if (idx < 96)   out96[idx] = 0.0f;
}

// ---------------- K1: fused h = x@W  and  degree scatter ----------------
template<int FIN>
__global__ void k_gemm_deg(const float* __restrict__ xin, const float* __restrict__ W,
                           int n, int layer) {
    int idx = blockIdx.x * blockDim.x + threadIdx.x;
    const float* x = (layer == 0) ? xin : g_xp[layer - 1];
    int gemmN = n * F;
    if (idx < gemmN) {
        int i = idx / F, j = idx % F;
        float acc = 0.0f;
        #pragma unroll 8
        for (int k = 0; k < FIN; k++) acc += x[i * FIN + k] * W[k * F + j];
        g_h[idx] = acc;
    } else {
        int e = idx - gemmN;
        if (e < E_EDGES) {
            float w = g_ew[layer][e];
            if (w > 0.0f) atomicAdd(&g_deg[layer][g_col[layer][e]], w);
        }
    }
}

// ---------------- K2: dinv + self-loop contribution (plain stores) ----------------
__global__ void k_dinv(int n, int layer) {
    int i = blockIdx.x * blockDim.x + threadIdx.x;
    if (i >= n) return;
    float d  = g_deg[layer][i];
    float dv = (d > 0.0f) ? __frsqrt_rn(fmaxf(d, 1e-12f)) : 0.0f;
    g_dinv[i] = dv;
    float s = dv * dv;   // self-loop norm: dinv[i]*1*dinv[i]
    #pragma unroll
    for (int f = 0; f < F; f++) g_out[i * F + f] = s * g_h[i * F + f];
}

// ---------------- K3: edge scatter, 16 threads per edge ----------------
__global__ void k_scatter(int layer) {
    int idx = blockIdx.x * blockDim.x + threadIdx.x;
    if (idx >= E_EDGES * F) return;
    int e = idx >> 4, f = idx & 15;
    float w = g_ew[layer][e];
    if (w <= 0.0f) return;
    int r = g_row[layer][e], c = g_col[layer][e];
    float norm = g_dinv[r] * w * g_dinv[c];
    atomicAdd(&g_out[c * F + f], norm * g_h[r * F + f]);
}

// ---------------- K4: single-block relu + score + exact top-k + gather ----------------
// key = (~monotonic(float score) << 32) | idx  -> ascending sort == descending score,
// ties broken by lowest index first (matches jax.lax.top_k).
template<int NL, int SORTN>
__global__ void __launch_bounds__(1024) k_pool(const float* __restrict__ b,
                                               const float* __restrict__ pw, int layer) {
    __shared__ unsigned long long keys[SORTN];
    const int K = (NL + 1) / 2;
    int tid = threadIdx.x;

    float npw = 0.0f;
    #pragma unroll
    for (int f = 0; f < F; f++) { float v = pw[f]; npw += v * v; }
    npw = sqrtf(npw);

    for (int i = tid; i < SORTN; i += blockDim.x) {
        unsigned long long key;
        if (i < NL) {
            float s = 0.0f;
            #pragma unroll
            for (int f = 0; f < F; f++) {
                float v = g_out[i * F + f] + b[f];
                v = v > 0.0f ? v : 0.0f;      // relu
                g_xr[i * F + f] = v;
                s += v * pw[f];
            }
            float sc = tanhf(s / npw);
            int bits = __float_as_int(sc);
            unsigned int ka = (bits >= 0) ? (0x80000000u + (unsigned int)bits)
                                          : ~(unsigned int)bits;    // ascending float key
            unsigned int kd = ~ka;                                   // descending
            key = ((unsigned long long)kd << 32) | (unsigned int)i;
        } else {
            key = 0xFFFFFFFFFFFFFFFFULL;   // pad sorts last
        }
        keys[i] = key;
    }
    __syncthreads();

    for (int size = 2; size <= SORTN; size <<= 1) {
        for (int stride = size >> 1; stride > 0; stride >>= 1) {
            for (int t = tid; t < SORTN / 2; t += blockDim.x) {
                int i = 2 * t - (t & (stride - 1));
                int j = i + stride;
                bool asc = ((i & size) == 0);
                unsigned long long a = keys[i], c = keys[j];
                if ((a > c) == asc) { keys[i] = c; keys[j] = a; }
            }
            __syncthreads();
        }
    }

    for (int i = tid; i < NL; i += blockDim.x) g_pos[i] = -1;
    __syncthreads();

    float* xnext = g_xp[layer];
    for (int j = tid; j < K; j += blockDim.x) {
        unsigned long long key = keys[j];
        int p = (int)(unsigned int)(key & 0xFFFFFFFFu);
        g_pos[p] = j;
        unsigned int kd = (unsigned int)(key >> 32);
        unsigned int ka = ~kd;
        int bits = (ka >= 0x80000000u) ? (int)(ka - 0x80000000u) : (int)(~ka);
        float val = __int_as_float(bits);
        #pragma unroll
        for (int f = 0; f < F; f++) xnext[j * F + f] = g_xr[p * F + f] * val;
    }
}

// ---------------- K5: edge remap ----------------
__global__ void k_remap(int layer) {
    int e = blockIdx.x * blockDim.x + threadIdx.x;
    if (e >= E_EDGES) return;
    int r = g_row[layer][e], c = g_col[layer][e];
    float w = g_ew[layer][e];
    int nr = g_pos[r], nc = g_pos[c];
    bool valid = (nr >= 0) && (nc >= 0) && (w > 0.0f);
    g_row[layer + 1][e] = valid ? nr : 0;
    g_col[layer + 1][e] = valid ? nc : 0;
    g_ew [layer + 1][e] = valid ? w : 0.0f;
}

// ---------------- FC: split-K matvec ----------------
// MODE: 0 = g_xp[3] -> g_h1, 1 = g_h1 -> g_h2, 2 = g_h2 -> outp
template<int IN, int OUT, int CH, int MODE>
__global__ void k_fc(const float* __restrict__ W, const float* __restrict__ b,
                     float* __restrict__ outp) {
    const float* hin = (MODE == 0) ? (const float*)g_xp[3] : (MODE == 1) ? g_h1 : g_h2;
    float* hout      = (MODE == 0) ? g_h1 : (MODE == 1) ? g_h2 : outp;
    int nOutBlocks = OUT / blockDim.x;
    int ob = blockIdx.x % nOutBlocks;
    int ch = blockIdx.x / nOutBlocks;
    int j = ob * blockDim.x + threadIdx.x;
    const int RPC = IN / CH;
    int i0 = ch * RPC;
    float acc = (ch == 0) ? b[j] : 0.0f;
    for (int i = i0; i < i0 + RPC; i++) acc += hin[i] * W[i * OUT + j];
    atomicAdd(&hout[j], acc);
}

// ---------------- launch ----------------
extern "C" void kernel_launch(void* const* d_in, const int* in_sizes, int n_in,
                              void* d_out, int out_size) {
    const float* x   = (const float*)d_in[0];
    const int*   ei  = (const int*)d_in[1];
    const float* W[4]  = {(const float*)d_in[3], (const float*)d_in[5],
                          (const float*)d_in[7], (const float*)d_in[9]};
    const float* bb[4] = {(const float*)d_in[4], (const float*)d_in[6],
                          (const float*)d_in[8], (const float*)d_in[10]};
    const float* pw[4] = {(const float*)d_in[11], (const float*)d_in[12],
                          (const float*)d_in[13], (const float*)d_in[14]};
    const float* fw1 = (const float*)d_in[15];
    const float* fb1 = (const float*)d_in[16];
    const float* fw2 = (const float*)d_in[17];
    const float* fb2 = (const float*)d_in[18];
    const float* fw3 = (const float*)d_in[19];
    const float* fb3 = (const float*)d_in[20];
    float* out = (float*)d_out;

    const int ns[4] = {1408, 704, 352, 176};

    k_init<<<(E_EDGES + 255) / 256, 256>>>(ei, out);

    // ---- layer 0 (FIN = 128) ----
    {
        int n = ns[0];
        int tot = n * F + E_EDGES;
        k_gemm_deg<128><<<(tot + 255) / 256, 256>>>(x, W[0], n, 0);
        k_dinv<<<(n + 255) / 256, 256>>>(n, 0);
        k_scatter<<<(E_EDGES * F + 255) / 256, 256>>>(0);
        k_pool<1408, 2048><<<1, 1024>>>(bb[0], pw[0], 0);
        k_remap<<<(E_EDGES + 255) / 256, 256>>>(0);
    }
    // ---- layer 1 ----
    {
        int n = ns[1];
        int tot = n * F + E_EDGES;
        k_gemm_deg<16><<<(tot + 255) / 256, 256>>>(x, W[1], n, 1);
        k_dinv<<<(n + 255) / 256, 256>>>(n, 1);
        k_scatter<<<(E_EDGES * F + 255) / 256, 256>>>(1);
        k_pool<704, 1024><<<1, 1024>>>(bb[1], pw[1], 1);
        k_remap<<<(E_EDGES + 255) / 256, 256>>>(1);
    }
    // ---- layer 2 ----
    {
        int n = ns[2];
        int tot = n * F + E_EDGES;
        k_gemm_deg<16><<<(tot + 255) / 256, 256>>>(x, W[2], n, 2);
        k_dinv<<<(n + 255) / 256, 256>>>(n, 2);
        k_scatter<<<(E_EDGES * F + 255) / 256, 256>>>(2);
        k_pool<352, 512><<<1, 1024>>>(bb[2], pw[2], 2);
        k_remap<<<(E_EDGES + 255) / 256, 256>>>(2);
    }
    // ---- layer 3 (no remap needed afterwards) ----
    {
        int n = ns[3];
        int tot = n * F + E_EDGES;
        k_gemm_deg<16><<<(tot + 255) / 256, 256>>>(x, W[3], n, 3);
        k_dinv<<<(n + 255) / 256, 256>>>(n, 3);
        k_scatter<<<(E_EDGES * F + 255) / 256, 256>>>(3);
        k_pool<176, 256><<<1, 1024>>>(bb[3], pw[3], 3);
    }

    // ---- FC head ----
    k_fc<1408, 1024, 8, 0><<<(1024 / 128) * 8, 128>>>(fw1, fb1, out);
    k_fc<1024, 512, 8, 1><<<(512 / 128) * 8, 128>>>(fw2, fb2, out);
    k_fc<512, 96, 4, 2><<<4, 96>>>(fw3, fb3, out);
}

// round 2
// speedup vs baseline: 1.2463x; 1.2463x over previous
#include <cuda_runtime.h>
#include <math.h>

#define E0    90112
#define F     16
#define N0    1408
#define GRID  128
#define BLOCK 512
#define NT    (GRID * BLOCK)

// ---------------- persistent device state ----------------
__device__ unsigned int g_arrive;          // barrier arrival counter (self-resetting)
__device__ unsigned int g_gen;             // barrier generation (monotonic, never reset)
__device__ int          g_ecnt[4];         // compacted edge count per layer ([0] unused)
__device__ __align__(16) float g_h  [N0 * F];
__device__ __align__(16) float g_out[N0 * F];
__device__ __align__(16) float g_xp [4][704 * F];
__device__ float g_deg [4][N0];            // edge-degree (self-loop added at use); self-cleaning
__device__ float g_dinv[N0];
__device__ int   g_pos [N0];
__device__ int   g_row [4][E0];
__device__ int   g_col [4][E0];
__device__ float g_h1[1024];
__device__ float g_h2[512];

// ---------------- grid barrier (sense via generation counter) ----------------
__device__ __forceinline__ void gsync() {
    __threadfence();
    __syncthreads();
    if (threadIdx.x == 0) {
        unsigned int gen = *((volatile unsigned int*)&g_gen);
        unsigned int old = atomicAdd(&g_arrive, 1u);
        if (old == GRID - 1u) {
            atomicExch(&g_arrive, 0u);
            __threadfence();
            atomicAdd(&g_gen, 1u);
        } else {
            while (*((volatile unsigned int*)&g_gen) == gen) {}
        }
        __threadfence();
    }
    __syncthreads();
}

__device__ __forceinline__ void red_add_v4(float* addr, float a, float b, float c, float d) {
    asm volatile("red.global.add.v4.f32 [%0], {%1, %2, %3, %4};"
                 :: "l"(addr), "f"(a), "f"(b), "f"(c), "f"(d) : "memory");
}

__global__ void __launch_bounds__(BLOCK, 1) gcn_fused(
    const float* __restrict__ x, const int* __restrict__ ei,
    const float* __restrict__ W0, const float* __restrict__ b0,
    const float* __restrict__ W1, const float* __restrict__ b1,
    const float* __restrict__ W2, const float* __restrict__ b2,
    const float* __restrict__ W3, const float* __restrict__ b3,
    const float* __restrict__ pw0, const float* __restrict__ pw1,
    const float* __restrict__ pw2, const float* __restrict__ pw3,
    const float* __restrict__ fw1, const float* __restrict__ fb1,
    const float* __restrict__ fw2, const float* __restrict__ fb2,
    const float* __restrict__ fw3, const float* __restrict__ fb3,
    float* __restrict__ out)
{
    const int gtid = blockIdx.x * BLOCK + threadIdx.x;
    __shared__ unsigned long long s_keys[2048];

    const int   ns[4]    = {1408, 704, 352, 176};
    const int   sortn[4] = {2048, 1024, 512, 256};
    const float* Ws[4]  = {W0, W1, W2, W3};
    const float* bs[4]  = {b0, b1, b2, b3};
    const float* pws[4] = {pw0, pw1, pw2, pw3};

    // ---------------- init: copy edges, layer-0 degree, seed accumulators ----------------
    for (int idx = gtid; idx < E0; idx += NT) {
        int r = ei[idx], c = ei[E0 + idx];
        g_row[0][idx] = r;
        g_col[0][idx] = c;
        atomicAdd(&g_deg[0][c], 1.0f);
    }
    if (gtid < 1024) g_h1[gtid] = fb1[gtid];
    if (gtid < 512)  g_h2[gtid] = fb2[gtid];
    if (gtid < 96)   out[gtid]  = fb3[gtid];
    if (gtid == 0) { g_ecnt[1] = 0; g_ecnt[2] = 0; g_ecnt[3] = 0; }
    gsync();

    // ---------------- 4 GCN layers ----------------
    for (int l = 0; l < 4; l++) {
        const int n  = ns[l];
        const int El = (l == 0) ? E0 : g_ecnt[l];
        const float* Wl = Ws[l];

        // Phase A: h = x@W ; dinv from precomputed degree ; self-loop seed of g_out
        {
            const float* xin = (l == 0) ? x : g_xp[l - 1];
            const int gemmN = n * F;
            for (int idx = gtid; idx < gemmN; idx += NT) {
                int i = idx >> 4, j = idx & 15;
                float acc = 0.0f;
                if (l == 0) {
                    const float* xr = xin + i * 128;
                    #pragma unroll 16
                    for (int k = 0; k < 128; k++) acc += xr[k] * Wl[k * F + j];
                } else {
                    const float* xr = xin + i * F;
                    #pragma unroll
                    for (int k = 0; k < F; k++) acc += xr[k] * Wl[k * F + j];
                }
                g_h[idx] = acc;
                float deg = g_deg[l][i] + 1.0f;   // + self loop
                float dv  = __frsqrt_rn(deg);
                g_out[idx] = dv * dv * acc;
                if (j == 0) g_dinv[i] = dv;
            }
        }
        gsync();

        // Phase B: edge scatter (vector reductions) + self-clean deg[l]
        for (int e = gtid; e < El; e += NT) {
            int r = g_row[l][e], c = g_col[l][e];
            float norm = g_dinv[r] * g_dinv[c];
            const float4* hr = (const float4*)&g_h[r * F];
            float* oc = &g_out[c * F];
            #pragma unroll
            for (int q = 0; q < 4; q++) {
                float4 hv = hr[q];
                red_add_v4(oc + 4 * q, norm * hv.x, norm * hv.y, norm * hv.z, norm * hv.w);
            }
        }
        for (int i = gtid; i < n; i += NT) g_deg[l][i] = 0.0f;  // ready for next replay
        gsync();

        // Phase C: pool (block 0 only) — relu + score + exact bitonic top-k + gather
        if (blockIdx.x == 0) {
            const int NL = n, SORTN = sortn[l], K = (NL + 1) / 2;
            const float* bb = bs[l];
            const float* pw = pws[l];
            float npw = 0.0f;
            #pragma unroll
            for (int f = 0; f < F; f++) { float v = pw[f]; npw += v * v; }
            npw = sqrtf(npw);

            for (int i = threadIdx.x; i < NL; i += BLOCK) g_pos[i] = -1;

            for (int i = threadIdx.x; i < SORTN; i += BLOCK) {
                unsigned long long key;
                if (i < NL) {
                    float s = 0.0f;
                    #pragma unroll
                    for (int f = 0; f < F; f++) {
                        float v = g_out[i * F + f] + bb[f];
                        v = v > 0.0f ? v : 0.0f;
                        s += v * pw[f];
                    }
                    float sc = tanhf(s / npw);
                    int bits = __float_as_int(sc);
                    unsigned int ka = (bits >= 0) ? (0x80000000u + (unsigned int)bits)
                                                  : ~(unsigned int)bits;
                    key = ((unsigned long long)(~ka) << 32) | (unsigned int)i;
                } else {
                    key = 0xFFFFFFFFFFFFFFFFULL;
                }
                s_keys[i] = key;
            }
            __syncthreads();

            for (int size = 2; size <= SORTN; size <<= 1) {
                for (int stride = size >> 1; stride > 0; stride >>= 1) {
                    for (int t = threadIdx.x; t < SORTN / 2; t += BLOCK) {
                        int i = 2 * t - (t & (stride - 1));
                        int j = i + stride;
                        bool asc = ((i & size) == 0);
                        unsigned long long a = s_keys[i], c = s_keys[j];
                        if ((a > c) == asc) { s_keys[i] = c; s_keys[j] = a; }
                    }
                    __syncthreads();
                }
            }

            float* xnext = g_xp[l];
            for (int j = threadIdx.x; j < K; j += BLOCK) {
                unsigned long long key = s_keys[j];
                int p = (int)(unsigned int)(key & 0xFFFFFFFFu);
                g_pos[p] = j;
                unsigned int ka = ~(unsigned int)(key >> 32);
                int bits = (ka >= 0x80000000u) ? (int)(ka - 0x80000000u) : (int)(~ka);
                float val = __int_as_float(bits);
                #pragma unroll
                for (int f = 0; f < F; f++) {
                    float v = g_out[p * F + f] + bb[f];
                    v = v > 0.0f ? v : 0.0f;
                    xnext[j * F + f] = v * val;
                }
            }
        }
        gsync();

        // Phase D: remap + compact edges + degree for next layer
        if (l < 3) {
            for (int e = gtid; e < El; e += NT) {
                int nr = g_pos[g_row[l][e]];
                int nc = g_pos[g_col[l][e]];
                if (nr >= 0 && nc >= 0) {
                    int j = atomicAdd(&g_ecnt[l + 1], 1);
                    g_row[l + 1][j] = nr;
                    g_col[l + 1][j] = nc;
                    atomicAdd(&g_deg[l + 1][nc], 1.0f);
                }
            }
            gsync();
        }
    }

    // ---------------- FC head (split-K matvecs, bias pre-seeded) ----------------
    {   // fc1: 1408 -> 1024, 64 chunks of 22
        int t = gtid;                       // 65536 tasks exactly
        int j = t & 1023, ch = t >> 10;
        const float* hin = g_xp[3];
        int i0 = ch * 22;
        float acc = 0.0f;
        #pragma unroll
        for (int i = 0; i < 22; i++) acc += hin[i0 + i] * fw1[(i0 + i) * 1024 + j];
        atomicAdd(&g_h1[j], acc);
    }
    gsync();
    {   // fc2: 1024 -> 512, 128 chunks of 8
        int t = gtid;
        int j = t & 511, ch = t >> 9;
        int i0 = ch * 8;
        float acc = 0.0f;
        #pragma unroll
        for (int i = 0; i < 8; i++) acc += g_h1[i0 + i] * fw2[(i0 + i) * 512 + j];
        atomicAdd(&g_h2[j], acc);
    }
    gsync();
    if (gtid < 96 * 64) {  // fc3: 512 -> 96, 64 chunks of 8
        int j = gtid % 96, ch = gtid / 96;
        int i0 = ch * 8;
        float acc = 0.0f;
        #pragma unroll
        for (int i = 0; i < 8; i++) acc += g_h2[i0 + i] * fw3[(i0 + i) * 96 + j];
        atomicAdd(&out[j], acc);
    }
}

extern "C" void kernel_launch(void* const* d_in, const int* in_sizes, int n_in,
                              void* d_out, int out_size) {
    const float* x   = (const float*)d_in[0];
    const int*   ei  = (const int*)d_in[1];
    gcn_fused<<<GRID, BLOCK>>>(
        x, ei,
        (const float*)d_in[3],  (const float*)d_in[4],
        (const float*)d_in[5],  (const float*)d_in[6],
        (const float*)d_in[7],  (const float*)d_in[8],
        (const float*)d_in[9],  (const float*)d_in[10],
        (const float*)d_in[11], (const float*)d_in[12],
        (const float*)d_in[13], (const float*)d_in[14],
        (const float*)d_in[15], (const float*)d_in[16],
        (const float*)d_in[17], (const float*)d_in[18],
        (const float*)d_in[19], (const float*)d_in[20],
        (float*)d_out);
}

// round 3
// speedup vs baseline: 1.6079x; 1.2901x over previous
#include <cuda_runtime.h>
#include <math.h>

#define E0    90112
#define F     16
#define N0    1408
#define GRID  128
#define BLOCK 512
#define NT    (GRID * BLOCK)

// ---------------- persistent device state ----------------
__device__ unsigned int g_arrive;
__device__ unsigned int g_gen;             // monotonic generation
__device__ int          g_ecnt[4];         // compacted edge count per layer ([0] unused)
__device__ __align__(16) float g_h   [N0 * F];
__device__ __align__(16) float g_outA[N0 * F];      // conv accum, layers 0,2
__device__ __align__(16) float g_outB[704 * F];     // conv accum, layers 1,3
__device__ __align__(16) float g_xp3 [88 * F];      // final pooled features (FC input)
__device__ float g_deg [4][N0];            // edge-degree (self-loop added at use); self-cleaning
__device__ int   g_pos [N0];               // old -> new (or -1)
__device__ int   g_perm[704];              // new -> old
__device__ float g_val [704];              // tanh score of selected
__device__ int   g_row [4][E0];
__device__ int   g_col [4][E0];
__device__ float g_h1[1024];
__device__ float g_h2[512];

// ---------------- light grid barrier (CG-style acq/rel) ----------------
__device__ __forceinline__ void gsync() {
    __syncthreads();
    if (threadIdx.x == 0) {
        unsigned int gen;
        asm volatile("ld.acquire.gpu.u32 %0, [%1];" : "=r"(gen) : "l"(&g_gen) : "memory");
        unsigned int old;
        asm volatile("atom.add.release.gpu.u32 %0, [%1], 1;"
                     : "=r"(old) : "l"(&g_arrive) : "memory");
        if (old == GRID - 1u) {
            asm volatile("st.relaxed.gpu.u32 [%0], 0;" :: "l"(&g_arrive) : "memory");
            asm volatile("st.release.gpu.u32 [%0], %1;" :: "l"(&g_gen), "r"(gen + 1u) : "memory");
        } else {
            unsigned int cur;
            do {
                asm volatile("ld.acquire.gpu.u32 %0, [%1];" : "=r"(cur) : "l"(&g_gen) : "memory");
            } while (cur == gen);
        }
    }
    __syncthreads();
}

__device__ __forceinline__ void red_add_v4(float* addr, float a, float b, float c, float d) {
    asm volatile("red.global.add.v4.f32 [%0], {%1, %2, %3, %4};"
                 :: "l"(addr), "f"(a), "f"(b), "f"(c), "f"(d) : "memory");
}

// pool for layer l (block 0 only): relu+score+bitonic top-k; writes g_pos/g_perm/g_val
template<int NL, int SORTN>
__device__ void do_pool(unsigned long long* s_keys, const float* __restrict__ outbuf,
                        const float* __restrict__ bb, const float* __restrict__ pw,
                        bool write_xp3) {
    const int K = (NL + 1) / 2;
    float npw = 0.0f;
    #pragma unroll
    for (int f = 0; f < F; f++) { float v = pw[f]; npw += v * v; }
    npw = sqrtf(npw);

    for (int i = threadIdx.x; i < NL; i += BLOCK) g_pos[i] = -1;

    for (int i = threadIdx.x; i < SORTN; i += BLOCK) {
        unsigned long long key;
        if (i < NL) {
            float s = 0.0f;
            #pragma unroll
            for (int f = 0; f < F; f++) {
                float v = outbuf[i * F + f] + bb[f];
                v = v > 0.0f ? v : 0.0f;
                s += v * pw[f];
            }
            float sc = tanhf(s / npw);
            int bits = __float_as_int(sc);
            unsigned int ka = (bits >= 0) ? (0x80000000u + (unsigned int)bits)
                                          : ~(unsigned int)bits;
            key = ((unsigned long long)(~ka) << 32) | (unsigned int)i;
        } else {
            key = 0xFFFFFFFFFFFFFFFFULL;
        }
        s_keys[i] = key;
    }
    __syncthreads();

    for (int size = 2; size <= SORTN; size <<= 1) {
        for (int stride = size >> 1; stride > 0; stride >>= 1) {
            for (int t = threadIdx.x; t < SORTN / 2; t += BLOCK) {
                int i = 2 * t - (t & (stride - 1));
                int j = i + stride;
                bool asc = ((i & size) == 0);
                unsigned long long a = s_keys[i], c = s_keys[j];
                if ((a > c) == asc) { s_keys[i] = c; s_keys[j] = a; }
            }
            __syncthreads();
        }
    }

    for (int j = threadIdx.x; j < K; j += BLOCK) {
        unsigned long long key = s_keys[j];
        int p = (int)(unsigned int)(key & 0xFFFFFFFFu);
        unsigned int ka = ~(unsigned int)(key >> 32);
        int bits = (ka >= 0x80000000u) ? (int)(ka - 0x80000000u) : (int)(~ka);
        float val = __int_as_float(bits);
        g_pos[p] = j;
        g_perm[j] = p;
        g_val[j] = val;
        if (write_xp3) {
            #pragma unroll
            for (int f = 0; f < F; f++) {
                float v = outbuf[p * F + f] + bb[f];
                v = v > 0.0f ? v : 0.0f;
                g_xp3[j * F + f] = v * val;
            }
        }
    }
}

__global__ void __launch_bounds__(BLOCK, 1) gcn_fused(
    const float* __restrict__ x, const int* __restrict__ ei,
    const float* __restrict__ W0, const float* __restrict__ b0,
    const float* __restrict__ W1, const float* __restrict__ b1,
    const float* __restrict__ W2, const float* __restrict__ b2,
    const float* __restrict__ W3, const float* __restrict__ b3,
    const float* __restrict__ pw0, const float* __restrict__ pw1,
    const float* __restrict__ pw2, const float* __restrict__ pw3,
    const float* __restrict__ fw1, const float* __restrict__ fb1,
    const float* __restrict__ fw2, const float* __restrict__ fb2,
    const float* __restrict__ fw3, const float* __restrict__ fb3,
    float* __restrict__ out)
{
    const int gtid = blockIdx.x * BLOCK + threadIdx.x;
    const int lane = threadIdx.x & 31;
    __shared__ unsigned long long s_keys[2048];

    const int    ns[4]  = {1408, 704, 352, 176};
    const float* Ws[4]  = {W0, W1, W2, W3};
    const float* bs[4]  = {b0, b1, b2, b3};
    float* const obuf[4] = {g_outA, g_outB, g_outA, g_outB};

    // ---------- Phase M: init + edge copy + deg0 + gemm0 + zero outA + FC seeds ----------
    for (int idx = gtid; idx < E0; idx += NT) {
        int r = ei[idx], c = ei[E0 + idx];
        g_row[0][idx] = r;
        g_col[0][idx] = c;
        atomicAdd(&g_deg[0][c], 1.0f);
    }
    for (int idx = gtid; idx < N0 * F; idx += NT) {
        int i = idx >> 4, j = idx & 15;
        const float* xr = x + i * 128;
        float acc = 0.0f;
        #pragma unroll 16
        for (int k = 0; k < 128; k++) acc += xr[k] * W0[k * F + j];
        g_h[idx] = acc;
        g_outA[idx] = 0.0f;
    }
    if (gtid < 1024) g_h1[gtid] = fb1[gtid];
    if (gtid < 512)  g_h2[gtid] = fb2[gtid];
    if (gtid < 96)   out[gtid]  = fb3[gtid];
    if (gtid == 0) { g_ecnt[1] = 0; g_ecnt[2] = 0; g_ecnt[3] = 0; }
    gsync();

    // ---------- per layer: scatter | pool | (E: remap+gather+gemm) ----------
    for (int l = 0; l < 4; l++) {
        const int n  = ns[l];
        const int El = (l == 0) ? E0 : g_ecnt[l];
        float* outL  = obuf[l];
        const float* degL = g_deg[l];

        // Phase S: self-loop + edge scatter (norm from deg on the fly)
        for (int t = gtid; t < n + El; t += NT) {
            if (t < n) {
                float dv2 = 1.0f / (degL[t] + 1.0f);
                const float4* hr = (const float4*)&g_h[t * F];
                float* oc = &outL[t * F];
                #pragma unroll
                for (int q = 0; q < 4; q++) {
                    float4 hv = hr[q];
                    red_add_v4(oc + 4 * q, dv2 * hv.x, dv2 * hv.y, dv2 * hv.z, dv2 * hv.w);
                }
            } else {
                int e = t - n;
                int r = g_row[l][e], c = g_col[l][e];
                float norm = __frsqrt_rn(degL[r] + 1.0f) * __frsqrt_rn(degL[c] + 1.0f);
                const float4* hr = (const float4*)&g_h[r * F];
                float* oc = &outL[c * F];
                #pragma unroll
                for (int q = 0; q < 4; q++) {
                    float4 hv = hr[q];
                    red_add_v4(oc + 4 * q, norm * hv.x, norm * hv.y, norm * hv.z, norm * hv.w);
                }
            }
        }
        gsync();

        // Phase P: block 0 pools; other blocks self-clean deg[l] for next replay
        if (blockIdx.x == 0) {
            if (l == 0) do_pool<1408, 2048>(s_keys, outL, bs[0], pw0, false);
            if (l == 1) do_pool< 704, 1024>(s_keys, outL, bs[1], pw1, false);
            if (l == 2) do_pool< 352,  512>(s_keys, outL, bs[2], pw2, false);
            if (l == 3) do_pool< 176,  256>(s_keys, outL, bs[3], pw3, true);
        } else {
            int t0 = (blockIdx.x - 1) * BLOCK + threadIdx.x;
            for (int i = t0; i < n; i += (GRID - 1) * BLOCK) g_deg[l][i] = 0.0f;
        }
        gsync();

        // Phase E: remap+compact edges -> layer l+1, gather+gemm h, zero next out buffer
        if (l < 3) {
            const int Knew = ns[l + 1];
            const float* bb = bs[l];
            const float* Wn = Ws[l + 1];
            float* outN = obuf[l + 1];
            // nodes: fused gather + 16x16 gemm
            for (int idx = gtid; idx < Knew * F; idx += NT) {
                int j = idx >> 4, f2 = idx & 15;
                int p = g_perm[j];
                float val = g_val[j];
                const float* src = &outL[p * F];
                float acc = 0.0f;
                #pragma unroll
                for (int f = 0; f < F; f++) {
                    float v = src[f] + bb[f];
                    v = v > 0.0f ? v : 0.0f;
                    acc += v * Wn[f * F + f2];
                }
                g_h[idx] = acc * val;
                outN[idx] = 0.0f;
            }
            // edges: warp-aggregated compaction
            int iters = (El + NT - 1) / NT;
            for (int it = 0; it < iters; it++) {
                int e = it * NT + gtid;
                bool valid = false; int nr = 0, nc = 0;
                if (e < El) {
                    nr = g_pos[g_row[l][e]];
                    nc = g_pos[g_col[l][e]];
                    valid = (nr >= 0) && (nc >= 0);
                }
                unsigned int m = __ballot_sync(0xFFFFFFFFu, valid);
                if (m) {
                    int leader = __ffs(m) - 1;
                    int base = 0;
                    if (lane == leader) base = atomicAdd(&g_ecnt[l + 1], __popc(m));
                    base = __shfl_sync(0xFFFFFFFFu, base, leader);
                    if (valid) {
                        int ppos = base + __popc(m & ((1u << lane) - 1u));
                        g_row[l + 1][ppos] = nr;
                        g_col[l + 1][ppos] = nc;
                        atomicAdd(&g_deg[l + 1][nc], 1.0f);
                    }
                }
            }
            gsync();
        }
    }
    gsync();   // xp3 ready

    // ---------- FC head (split-K matvecs, bias pre-seeded) ----------
    {   // fc1: 1408 -> 1024, 64 chunks of 22
        int j = gtid & 1023, ch = gtid >> 10;
        int i0 = ch * 22;
        float acc = 0.0f;
        #pragma unroll
        for (int i = 0; i < 22; i++) acc += g_xp3[i0 + i] * fw1[(i0 + i) * 1024 + j];
        atomicAdd(&g_h1[j], acc);
    }
    gsync();
    {   // fc2: 1024 -> 512, 128 chunks of 8
        int j = gtid & 511, ch = gtid >> 9;
        int i0 = ch * 8;
        float acc = 0.0f;
        #pragma unroll
        for (int i = 0; i < 8; i++) acc += g_h1[i0 + i] * fw2[(i0 + i) * 512 + j];
        atomicAdd(&g_h2[j], acc);
    }
    gsync();
    if (gtid < 96 * 64) {  // fc3: 512 -> 96, 64 chunks of 8
        int j = gtid % 96, ch = gtid / 96;
        int i0 = ch * 8;
        float acc = 0.0f;
        #pragma unroll
        for (int i = 0; i < 8; i++) acc += g_h2[i0 + i] * fw3[(i0 + i) * 96 + j];
        atomicAdd(&out[j], acc);
    }
}

extern "C" void kernel_launch(void* const* d_in, const int* in_sizes, int n_in,
                              void* d_out, int out_size) {
    gcn_fused<<<GRID, BLOCK>>>(
        (const float*)d_in[0],  (const int*)d_in[1],
        (const float*)d_in[3],  (const float*)d_in[4],
        (const float*)d_in[5],  (const float*)d_in[6],
        (const float*)d_in[7],  (const float*)d_in[8],
        (const float*)d_in[9],  (const float*)d_in[10],
        (const float*)d_in[11], (const float*)d_in[12],
        (const float*)d_in[13], (const float*)d_in[14],
        (const float*)d_in[15], (const float*)d_in[16],
        (const float*)d_in[17], (const float*)d_in[18],
        (const float*)d_in[19], (const float*)d_in[20],
        (float*)d_out);
}

// round 4
// speedup vs baseline: 2.1313x; 1.3255x over previous
#include <cuda_runtime.h>
#include <math.h>

#define E0    90112
#define F     16
#define N0    1408
#define GRID  128
#define BLOCK 512
#define NT    (GRID * BLOCK)

// ---------------- persistent device state ----------------
__device__ unsigned int g_arrive;
__device__ unsigned int g_gen;             // monotonic generation
__device__ int          g_ecnt[4];         // compacted edge count per layer ([0] unused)
__device__ __align__(16) float g_h   [N0 * F];
__device__ __align__(16) float g_outA[N0 * F];      // conv accum, layers 0,2
__device__ __align__(16) float g_outB[704 * F];     // conv accum, layers 1,3
__device__ __align__(16) float g_xp3 [88 * F];      // final pooled features (FC input)
__device__ float g_deg [4][N0];            // edge-degree (self-loop added at use); self-cleaning
__device__ int   g_pos [N0];               // old -> new (or -1)
__device__ int   g_row [4][E0];
__device__ int   g_col [4][E0];
__device__ float g_h1[1024];
__device__ float g_h2[512];

// ---------------- light grid barrier (CG-style acq/rel) ----------------
__device__ __forceinline__ void gsync() {
    __syncthreads();
    if (threadIdx.x == 0) {
        unsigned int gen;
        asm volatile("ld.acquire.gpu.u32 %0, [%1];" : "=r"(gen) : "l"(&g_gen) : "memory");
        unsigned int old;
        asm volatile("atom.add.release.gpu.u32 %0, [%1], 1;"
                     : "=r"(old) : "l"(&g_arrive) : "memory");
        if (old == GRID - 1u) {
            asm volatile("st.relaxed.gpu.u32 [%0], 0;" :: "l"(&g_arrive) : "memory");
            asm volatile("st.release.gpu.u32 [%0], %1;" :: "l"(&g_gen), "r"(gen + 1u) : "memory");
        } else {
            unsigned int cur;
            do {
                asm volatile("ld.acquire.gpu.u32 %0, [%1];" : "=r"(cur) : "l"(&g_gen) : "memory");
            } while (cur == gen);
        }
    }
    __syncthreads();
}

__device__ __forceinline__ void red_add_v4(float* addr, float a, float b, float c, float d) {
    asm volatile("red.global.add.v4.f32 [%0], {%1, %2, %3, %4};"
                 :: "l"(addr), "f"(a), "f"(b), "f"(c), "f"(d) : "memory");
}

__global__ void __launch_bounds__(BLOCK, 1) gcn_fused(
    const float* __restrict__ x, const int* __restrict__ ei,
    const float* __restrict__ W0, const float* __restrict__ b0,
    const float* __restrict__ W1, const float* __restrict__ b1,
    const float* __restrict__ W2, const float* __restrict__ b2,
    const float* __restrict__ W3, const float* __restrict__ b3,
    const float* __restrict__ pw0, const float* __restrict__ pw1,
    const float* __restrict__ pw2, const float* __restrict__ pw3,
    const float* __restrict__ fw1, const float* __restrict__ fb1,
    const float* __restrict__ fw2, const float* __restrict__ fb2,
    const float* __restrict__ fw3, const float* __restrict__ fb3,
    float* __restrict__ out)
{
    const int gtid = blockIdx.x * BLOCK + threadIdx.x;
    const int lane = threadIdx.x & 31;
    __shared__ unsigned long long s_keys[N0];   // 11.3 KB, max layer size

    const int    ns[4]  = {1408, 704, 352, 176};
    const float* Ws[4]  = {W0, W1, W2, W3};
    const float* bs[4]  = {b0, b1, b2, b3};
    const float* pws[4] = {pw0, pw1, pw2, pw3};
    float* const obuf[4] = {g_outA, g_outB, g_outA, g_outB};

    // ---------- Phase M: init + edge copy + deg0 + gemm0 + zero outA + FC seeds ----------
    for (int idx = gtid; idx < E0; idx += NT) {
        int r = ei[idx], c = ei[E0 + idx];
        g_row[0][idx] = r;
        g_col[0][idx] = c;
        atomicAdd(&g_deg[0][c], 1.0f);
    }
    for (int idx = gtid; idx < N0 * F; idx += NT) {
        int i = idx >> 4, j = idx & 15;
        const float* xr = x + i * 128;
        float acc = 0.0f;
        #pragma unroll 16
        for (int k = 0; k < 128; k++) acc += xr[k] * W0[k * F + j];
        g_h[idx] = acc;
        g_outA[idx] = 0.0f;
    }
    if (gtid < 1024) g_h1[gtid] = fb1[gtid];
    if (gtid < 512)  g_h2[gtid] = fb2[gtid];
    if (gtid < 96)   out[gtid]  = fb3[gtid];
    if (gtid == 0) { g_ecnt[1] = 0; g_ecnt[2] = 0; g_ecnt[3] = 0; }
    gsync();

    // ---------- per layer: S (scatter) | P (rank-select+gather+gemm) | E (edge remap) ----------
    for (int l = 0; l < 4; l++) {
        const int n  = ns[l];
        const int K  = n >> 1;
        const int El = (l == 0) ? E0 : g_ecnt[l];
        float* outL  = obuf[l];
        const float* degL = g_deg[l];

        // Phase S: self-loop + edge scatter (norm from deg on the fly)
        for (int t = gtid; t < n + El; t += NT) {
            if (t < n) {
                float dv2 = 1.0f / (degL[t] + 1.0f);
                const float4* hr = (const float4*)&g_h[t * F];
                float* oc = &outL[t * F];
                #pragma unroll
                for (int q = 0; q < 4; q++) {
                    float4 hv = hr[q];
                    red_add_v4(oc + 4 * q, dv2 * hv.x, dv2 * hv.y, dv2 * hv.z, dv2 * hv.w);
                }
            } else {
                int e = t - n;
                int r = g_row[l][e], c = g_col[l][e];
                float norm = __frsqrt_rn(degL[r] + 1.0f) * __frsqrt_rn(degL[c] + 1.0f);
                const float4* hr = (const float4*)&g_h[r * F];
                float* oc = &outL[c * F];
                #pragma unroll
                for (int q = 0; q < 4; q++) {
                    float4 hv = hr[q];
                    red_add_v4(oc + 4 * q, norm * hv.x, norm * hv.y, norm * hv.z, norm * hv.w);
                }
            }
        }
        gsync();

        // Phase P: parallel rank-selection. Each block recomputes all n keys into its
        // own smem (redundant, communication-free); warp w ranks node i = global warp id.
        {
            for (int i = gtid; i < n; i += NT) g_deg[l][i] = 0.0f;   // self-clean for replay
            const float* pw = pws[l];
            const float* bb = bs[l];
            if (blockIdx.x * (BLOCK / 32) < n) {
                float npw = 0.0f;
                #pragma unroll
                for (int f = 0; f < F; f++) { float v = pw[f]; npw += v * v; }
                npw = sqrtf(npw);

                for (int i = threadIdx.x; i < n; i += BLOCK) {
                    float s = 0.0f;
                    #pragma unroll
                    for (int f = 0; f < F; f++) {
                        float v = outL[i * F + f] + bb[f];
                        v = v > 0.0f ? v : 0.0f;
                        s += v * pw[f];
                    }
                    float sc = tanhf(s / npw);
                    int bits = __float_as_int(sc);
                    unsigned int ka = (bits >= 0) ? (0x80000000u + (unsigned int)bits)
                                                  : ~(unsigned int)bits;
                    s_keys[i] = ((unsigned long long)(~ka) << 32) | (unsigned int)i;
                }
                __syncthreads();

                int i = blockIdx.x * (BLOCK / 32) + (threadIdx.x >> 5);
                if (i < n) {
                    unsigned long long ki = s_keys[i];
                    int cnt = 0;
                    for (int j = lane; j < n; j += 32) cnt += (s_keys[j] < ki) ? 1 : 0;
                    int rank = __reduce_add_sync(0xFFFFFFFFu, cnt);
                    if (rank < K) {
                        unsigned int ka = ~(unsigned int)(ki >> 32);
                        int bits = (ka >= 0x80000000u) ? (int)(ka - 0x80000000u) : (int)(~ka);
                        float val = __int_as_float(bits);
                        if (lane == 0) g_pos[i] = rank;
                        if (lane < F) {
                            if (l < 3) {
                                const float* Wn = Ws[l + 1];
                                float* outN = (l & 1) ? g_outA : g_outB;
                                float acc = 0.0f;
                                #pragma unroll
                                for (int f = 0; f < F; f++) {
                                    float v = outL[i * F + f] + bb[f];
                                    v = v > 0.0f ? v : 0.0f;
                                    acc += v * Wn[f * F + lane];
                                }
                                g_h[rank * F + lane] = acc * val;
                                outN[rank * F + lane] = 0.0f;
                            } else {
                                float v = outL[i * F + lane] + bb[lane];
                                v = v > 0.0f ? v : 0.0f;
                                g_xp3[rank * F + lane] = v * val;
                            }
                        }
                    } else if (lane == 0) {
                        g_pos[i] = -1;
                    }
                }
            }
        }
        gsync();

        // Phase E: remap + compact edges -> layer l+1 + degree count
        if (l < 3) {
            int iters = (El + NT - 1) / NT;
            for (int it = 0; it < iters; it++) {
                int e = it * NT + gtid;
                bool valid = false; int nr = 0, nc = 0;
                if (e < El) {
                    nr = g_pos[g_row[l][e]];
                    nc = g_pos[g_col[l][e]];
                    valid = (nr >= 0) && (nc >= 0);
                }
                unsigned int m = __ballot_sync(0xFFFFFFFFu, valid);
                if (m) {
                    int leader = __ffs(m) - 1;
                    int base = 0;
                    if (lane == leader) base = atomicAdd(&g_ecnt[l + 1], __popc(m));
                    base = __shfl_sync(0xFFFFFFFFu, base, leader);
                    if (valid) {
                        int ppos = base + __popc(m & ((1u << lane) - 1u));
                        g_row[l + 1][ppos] = nr;
                        g_col[l + 1][ppos] = nc;
                        atomicAdd(&g_deg[l + 1][nc], 1.0f);
                    }
                }
            }
            gsync();
        }
    }

    // ---------- FC head (split-K matvecs, bias pre-seeded) ----------
    {   // fc1: 1408 -> 1024, 64 chunks of 22
        int j = gtid & 1023, ch = gtid >> 10;
        int i0 = ch * 22;
        float acc = 0.0f;
        #pragma unroll
        for (int i = 0; i < 22; i++) acc += g_xp3[i0 + i] * fw1[(i0 + i) * 1024 + j];
        atomicAdd(&g_h1[j], acc);
    }
    gsync();
    {   // fc2: 1024 -> 512, 128 chunks of 8
        int j = gtid & 511, ch = gtid >> 9;
        int i0 = ch * 8;
        float acc = 0.0f;
        #pragma unroll
        for (int i = 0; i < 8; i++) acc += g_h1[i0 + i] * fw2[(i0 + i) * 512 + j];
        atomicAdd(&g_h2[j], acc);
    }
    gsync();
    if (gtid < 96 * 64) {  // fc3: 512 -> 96, 64 chunks of 8
        int j = gtid % 96, ch = gtid / 96;
        int i0 = ch * 8;
        float acc = 0.0f;
        #pragma unroll
        for (int i = 0; i < 8; i++) acc += g_h2[i0 + i] * fw3[(i0 + i) * 96 + j];
        atomicAdd(&out[j], acc);
    }
}

extern "C" void kernel_launch(void* const* d_in, const int* in_sizes, int n_in,
                              void* d_out, int out_size) {
    gcn_fused<<<GRID, BLOCK>>>(
        (const float*)d_in[0],  (const int*)d_in[1],
        (const float*)d_in[3],  (const float*)d_in[4],
        (const float*)d_in[5],  (const float*)d_in[6],
        (const float*)d_in[7],  (const float*)d_in[8],
        (const float*)d_in[9],  (const float*)d_in[10],
        (const float*)d_in[11], (const float*)d_in[12],
        (const float*)d_in[13], (const float*)d_in[14],
        (const float*)d_in[15], (const float*)d_in[16],
        (const float*)d_in[17], (const float*)d_in[18],
        (const float*)d_in[19], (const float*)d_in[20],
        (float*)d_out);
}